// round 6
// baseline (speedup 1.0000x reference)
#include <cuda_runtime.h>
#include <math.h>

#define N_GAUSS 4096
#define IMG_H 128
#define IMG_W 128
#define N_SEG 8
#define SEG_LEN (N_GAUSS / N_SEG)     // 512
#define N_TILES 64                    // 8x8 tiles of 16x16
#define TILE_PX 256
#define ALPHA_MIN (1.0f/255.0f)
#define ALPHA_MAX 0.999f
#define EPS2D 0.3f
#define NBUCKET 4096

// ---------------- scratch (device globals) ----------------
__device__ float4 d_geo[N_GAUSS];   // mx, my, rx, ry
__device__ float4 d_con[N_GAUSS];   // 0.5*ca, cb, 0.5*cc, op
__device__ float4 d_col[N_GAUSS];   // r, g, b, cutoff(=ln(255*op)+margin)
__device__ int    d_order[N_GAUSS];

// per (tile, segment, pixel) partial composites: (Cr, Cg, Cb, T)
__device__ float4 g_seg[N_TILES * N_SEG * TILE_PX];
__device__ int    g_cnt[N_TILES];

__device__ __forceinline__ int z_bucket(float z) {
    float f = (z - 2.0f) * (4096.0f / 6.0f);
    int b = (int)f;
    return min(max(b, 0), NBUCKET - 1);
}

// scoped RMW: release orders prior stores (via preceding bar), acquire orders
// subsequent loads. NO gpu-scope fence -> no CCTL.IVALL L1 flush (R3 lesson).
__device__ __forceinline__ int atomicAddAcqRelGpu(int* p, int v) {
    int old;
    asm volatile("atom.acq_rel.gpu.add.s32 %0, [%1], %2;"
                 : "=r"(old) : "l"(p), "r"(v) : "memory");
    return old;
}

// ---------------- kernel 1: per-gaussian projection / conic ----------------
__global__ void prep_kernel(const float* __restrict__ Ks,
                            const float* __restrict__ vm,
                            const float* __restrict__ means,
                            const float* __restrict__ quats,
                            const float* __restrict__ scales,
                            const float* __restrict__ ops,
                            const float* __restrict__ rgb)
{
    int i = blockIdx.x * blockDim.x + threadIdx.x;
    if (blockIdx.x == 0 && threadIdx.x < N_TILES) g_cnt[threadIdx.x] = 0;
    if (i >= N_GAUSS) return;

    float mx0 = means[i*3+0], my0 = means[i*3+1], mz0 = means[i*3+2];
    float qw = quats[i*4+0], qx = quats[i*4+1], qy = quats[i*4+2], qz = quats[i*4+3];
    float s0 = scales[i*3+0], s1 = scales[i*3+1], s2 = scales[i*3+2];
    float op = ops[i];
    float cr = rgb[i*3+0], cg = rgb[i*3+1], cb2 = rgb[i*3+2];

    float R00 = vm[0],  R01 = vm[1],  R02 = vm[2],  T0 = vm[3];
    float R10 = vm[4],  R11 = vm[5],  R12 = vm[6],  T1 = vm[7];
    float R20 = vm[8],  R21 = vm[9],  R22 = vm[10], T2 = vm[11];

    float x = R00*mx0 + R01*my0 + R02*mz0 + T0;
    float y = R10*mx0 + R11*my0 + R12*mz0 + T1;
    float z = R20*mx0 + R21*my0 + R22*mz0 + T2;

    float zs = (fabsf(z) < 1e-6f) ? 1e-6f : z;
    float rz = __fdividef(1.0f, zs);

    float qn = rsqrtf(qw*qw + qx*qx + qy*qy + qz*qz);
    qw *= qn; qx *= qn; qy *= qn; qz *= qn;
    float r00 = 1.f - 2.f*(qy*qy + qz*qz), r01 = 2.f*(qx*qy - qw*qz), r02 = 2.f*(qx*qz + qw*qy);
    float r10 = 2.f*(qx*qy + qw*qz), r11 = 1.f - 2.f*(qx*qx + qz*qz), r12 = 2.f*(qy*qz - qw*qx);
    float r20 = 2.f*(qx*qz - qw*qy), r21 = 2.f*(qy*qz + qw*qx), r22 = 1.f - 2.f*(qx*qx + qy*qy);

    float m00 = r00*s0, m01 = r01*s1, m02 = r02*s2;
    float m10 = r10*s0, m11 = r11*s1, m12 = r12*s2;
    float m20 = r20*s0, m21 = r21*s1, m22 = r22*s2;

    float c00 = m00*m00 + m01*m01 + m02*m02;
    float c01 = m00*m10 + m01*m11 + m02*m12;
    float c02 = m00*m20 + m01*m21 + m02*m22;
    float c11 = m10*m10 + m11*m11 + m12*m12;
    float c12 = m10*m20 + m11*m21 + m12*m22;
    float c22 = m20*m20 + m21*m21 + m22*m22;

    float t00 = R00*c00 + R01*c01 + R02*c02;
    float t01 = R00*c01 + R01*c11 + R02*c12;
    float t02 = R00*c02 + R01*c12 + R02*c22;
    float t10 = R10*c00 + R11*c01 + R12*c02;
    float t11 = R10*c01 + R11*c11 + R12*c12;
    float t12 = R10*c02 + R11*c12 + R12*c22;
    float t20 = R20*c00 + R21*c01 + R22*c02;
    float t21 = R20*c01 + R21*c11 + R22*c12;
    float t22 = R20*c02 + R21*c12 + R22*c22;
    float cc00 = t00*R00 + t01*R01 + t02*R02;
    float cc01 = t00*R10 + t01*R11 + t02*R12;
    float cc02 = t00*R20 + t01*R21 + t02*R22;
    float cc11 = t10*R10 + t11*R11 + t12*R12;
    float cc12 = t10*R20 + t11*R21 + t12*R22;
    float cc22 = t20*R20 + t21*R21 + t22*R22;

    float fx = Ks[0], fy = Ks[4], cxK = Ks[2], cyK = Ks[5];
    float j00 = fx*rz, j02 = -fx*x*rz*rz;
    float j11 = fy*rz, j12 = -fy*y*rz*rz;

    float a2 = j00*j00*cc00 + 2.f*j00*j02*cc02 + j02*j02*cc22;
    float b2 = j00*(cc01*j11 + cc02*j12) + j02*(cc12*j11 + cc22*j12);
    float c2 = j11*j11*cc11 + 2.f*j11*j12*cc12 + j12*j12*cc22;

    float a = a2 + EPS2D;
    float c = c2 + EPS2D;
    float b = b2;
    float det = a*c - b*b;
    bool valid = (z > 0.01f) && (z < 100.0f) && (det > 0.0f);
    float dets = (det > 0.0f) ? det : 1.0f;
    float rdet = __fdividef(1.0f, dets);
    float ica =  c * rdet;
    float icb = -b * rdet;
    float icc =  a * rdet;

    float mpx = fx*x*rz + cxK;
    float mpy = fy*y*rz + cyK;
    float smax = __logf(255.0f * op);

    float rx = -1.0f, ry = -1.0f;
    if (valid && smax > 0.0f) {
        float inv = 2.0f * smax * dets;
        rx = sqrtf(inv * icc) * 1.0001f + 0.01f;
        ry = sqrtf(inv * ica) * 1.0001f + 0.01f;
    }

    d_geo[i] = make_float4(mpx, mpy, rx, ry);
    d_con[i] = make_float4(0.5f*ica, icb, 0.5f*icc, op);
    d_col[i] = make_float4(cr, cg, cb2, smax + 0.02f);
}

// ---------------- kernel 2: all-shared bucket argsort (one block) ----------------
__global__ void sort_kernel(const float* __restrict__ vm,
                            const float* __restrict__ means)
{
    __shared__ int            hist[NBUCKET];       // counts -> start -> cursor -> end
    __shared__ unsigned int   sk[N_GAUSS];
    __shared__ unsigned short si[N_GAUSS];
    __shared__ int            warpsums[32];

    const int t = threadIdx.x;           // 1024 threads
    const int lane = t & 31, wid = t >> 5;

    float R20 = vm[8], R21 = vm[9], R22 = vm[10], T2 = vm[11];

    for (int i = t; i < NBUCKET; i += 1024) hist[i] = 0;
    __syncthreads();

    unsigned int keys[4];
    int buck[4];
    #pragma unroll
    for (int c = 0; c < 4; c++) {
        int i = c * 1024 + t;
        float z = R20*means[i*3+0] + R21*means[i*3+1] + R22*means[i*3+2] + T2;
        keys[c] = __float_as_uint(z);
        int b = z_bucket(z);
        buck[c] = b;
        atomicAdd(&hist[b], 1);
    }
    __syncthreads();

    int h0 = hist[t*4+0], h1 = hist[t*4+1], h2 = hist[t*4+2], h3 = hist[t*4+3];
    int s = h0 + h1 + h2 + h3;
    int sc = s;
    #pragma unroll
    for (int o = 1; o < 32; o <<= 1) {
        int v = __shfl_up_sync(0xffffffffu, sc, o);
        if (lane >= o) sc += v;
    }
    if (lane == 31) warpsums[wid] = sc;
    __syncthreads();
    if (wid == 0) {
        int v = warpsums[lane];
        int vs = v;
        #pragma unroll
        for (int o = 1; o < 32; o <<= 1) {
            int u = __shfl_up_sync(0xffffffffu, vs, o);
            if (lane >= o) vs += u;
        }
        warpsums[lane] = vs - v;
    }
    __syncthreads();
    int excl = (sc - s) + warpsums[wid];
    hist[t*4+0] = excl;
    hist[t*4+1] = excl + h0;
    hist[t*4+2] = excl + h0 + h1;
    hist[t*4+3] = excl + h0 + h1 + h2;
    __syncthreads();

    #pragma unroll
    for (int c = 0; c < 4; c++) {
        int i = c * 1024 + t;
        int pos = atomicAdd(&hist[buck[c]], 1);
        sk[pos] = keys[c];
        si[pos] = (unsigned short)i;
    }
    __syncthreads();

    #pragma unroll
    for (int c = 0; c < 4; c++) {
        int slot = c * 1024 + t;
        unsigned int k = sk[slot];
        int id = si[slot];
        int b = z_bucket(__uint_as_float(k));
        int lo = (b > 0) ? hist[b-1] : 0;    // end[b-1] == start[b]
        int hi = hist[b];                     // end[b]
        int rank = 0;
        for (int j = lo; j < hi; j++) {
            unsigned int kj = sk[j];
            int ij = si[j];
            rank += (kj < k) || (kj == k && ij < id);
        }
        d_order[lo + rank] = id;
    }
}

// ---------------- kernel 3: render + fused last-CTA combine ----------------
__global__ void __launch_bounds__(256) render_kernel(float* __restrict__ out)
{
    const int tile = blockIdx.x;      // 0..63
    const int seg  = blockIdx.y;      // 0..7
    const int tx = tile & 7, ty = tile >> 3;
    const int lx = threadIdx.x & 15, ly = threadIdx.x >> 4;
    const float px = tx*16 + lx + 0.5f;
    const float py = ty*16 + ly + 0.5f;
    const float tileX0 = tx*16 + 0.5f, tileX1 = tileX0 + 15.0f;
    const float tileY0 = ty*16 + 0.5f, tileY1 = tileY0 + 15.0f;

    __shared__ float2 smxy[256];
    __shared__ float4 scon[256];
    __shared__ float4 scol[256];
    __shared__ int swcnt[8];
    __shared__ int sIsLast;

    const int lane = threadIdx.x & 31;
    const int wid  = threadIdx.x >> 5;

    float T = 1.0f, Cr = 0.0f, Cg = 0.0f, Cb = 0.0f;

    #pragma unroll
    for (int chunk = 0; chunk < SEG_LEN / 256; chunk++) {
        // cull + compact 256 gaussians into shared (indirect via d_order)
        int ord = d_order[seg * SEG_LEN + chunk * 256 + threadIdx.x];
        float4 geo = d_geo[ord];
        bool flag = (geo.z > 0.0f)
                 && (geo.x + geo.z >= tileX0) && (geo.x - geo.z <= tileX1)
                 && (geo.y + geo.w >= tileY0) && (geo.y - geo.w <= tileY1);
        unsigned m = __ballot_sync(0xffffffffu, flag);
        __syncthreads();                      // prior chunk's shared reads done
        if (lane == 0) swcnt[wid] = __popc(m);
        __syncthreads();
        int base = 0, total = 0;
        #pragma unroll
        for (int w = 0; w < 8; w++) {
            int cw = swcnt[w];
            if (w < wid) base += cw;
            total += cw;
        }
        int pos = base + __popc(m & ((1u << lane) - 1u));
        if (flag) {
            smxy[pos] = make_float2(geo.x, geo.y);
            scon[pos] = d_con[ord];
            scol[pos] = d_col[ord];
        }
        __syncthreads();

        for (int i = 0; i < total; i++) {
            if ((i & 31) == 0 && __all_sync(0xffffffffu, T < 1e-6f)) break;
            float2 mu = smxy[i];
            float4 co = scon[i];           // (0.5a, b, 0.5c, op)
            float dx = px - mu.x;
            float dy = py - mu.y;
            float sig = fmaf(co.x, dx*dx, fmaf(co.z, dy*dy, co.y*(dx*dy)));
            float4 col = scol[i];          // (r, g, b, cutoff)
            bool pre = (sig >= 0.0f) && (sig <= col.w);
            if (__any_sync(0xffffffffu, pre)) {
                float al = fminf(co.w * __expf(-sig), ALPHA_MAX);
                bool keep = (sig >= 0.0f) && (al >= ALPHA_MIN);
                float w = keep ? al * T : 0.0f;
                Cr = fmaf(w, col.x, Cr);
                Cg = fmaf(w, col.y, Cg);
                Cb = fmaf(w, col.z, Cb);
                T -= w;
            }
        }
    }

    g_seg[(tile * N_SEG + seg) * TILE_PX + threadIdx.x] = make_float4(Cr, Cg, Cb, T);

    // last CTA of this tile combines the 8 segment partials.
    __syncthreads();   // all partial stores issued before the release-RMW
    if (threadIdx.x == 0)
        sIsLast = (atomicAddAcqRelGpu(&g_cnt[tile], 1) == N_SEG - 1) ? 1 : 0;
    __syncthreads();   // broadcast + CTA-scope ordering after t0's acquire

    if (sIsLast) {
        const float4* basep = &g_seg[tile * N_SEG * TILE_PX + threadIdx.x];
        float aCr = 0.0f, aCg = 0.0f, aCb = 0.0f, aT = 1.0f;
        #pragma unroll
        for (int s = 0; s < N_SEG; s++) {
            float4 p = __ldcg(basep + s * TILE_PX);   // L1-bypass: reads L2
            aCr = fmaf(aT, p.x, aCr);
            aCg = fmaf(aT, p.y, aCg);
            aCb = fmaf(aT, p.z, aCb);
            aT *= p.w;
        }
        int x = tx*16 + lx, y = ty*16 + ly;
        int p = y * IMG_W + x;
        out[p]                 = aCr;
        out[IMG_H*IMG_W + p]   = aCg;
        out[2*IMG_H*IMG_W + p] = aCb;
    }
}

// ---------------- launch ----------------
extern "C" void kernel_launch(void* const* d_in, const int* in_sizes, int n_in,
                              void* d_out, int out_size)
{
    const float* Ks     = (const float*)d_in[0];
    const float* vm     = (const float*)d_in[1];
    const float* means  = (const float*)d_in[2];
    const float* quats  = (const float*)d_in[3];
    const float* scales = (const float*)d_in[4];
    const float* ops    = (const float*)d_in[5];
    const float* rgb    = (const float*)d_in[6];
    float* out = (float*)d_out;

    prep_kernel<<<32, 128>>>(Ks, vm, means, quats, scales, ops, rgb);
    sort_kernel<<<1, 1024>>>(vm, means);
    render_kernel<<<dim3(N_TILES, N_SEG), 256>>>(out);
}

// round 7
// speedup vs baseline: 1.0992x; 1.0992x over previous
#include <cuda_runtime.h>
#include <math.h>

#define N_GAUSS 4096
#define IMG_H 128
#define IMG_W 128
#define N_SEG 16
#define SEG_LEN (N_GAUSS / N_SEG)    // 256
#define N_TILES 64                   // 8x8 tiles of 16x16
#define TILE_PX 256
#define ALPHA_MIN (1.0f/255.0f)
#define ALPHA_MAX 0.999f
#define EPS2D 0.3f
#define NBUCKET 4096

// ---------------- scratch (device globals) ----------------
__device__ float4 d_geo[N_GAUSS];   // mx, my, rx, ry
__device__ float4 d_con[N_GAUSS];   // 0.5*ca, cb, 0.5*cc, op
__device__ float4 d_col[N_GAUSS];   // r, g, b, cutoff(=ln(255*op)+margin)
__device__ int    d_order[N_GAUSS];

// per (tile, segment, pixel) partial composites: (Cr, Cg, Cb, T)
__device__ float4 g_seg[N_TILES * N_SEG * TILE_PX];
__device__ int    g_cnt[N_TILES];

__device__ __forceinline__ int z_bucket(float z) {
    float f = (z - 2.0f) * (4096.0f / 6.0f);
    int b = (int)f;
    return min(max(b, 0), NBUCKET - 1);
}

// scoped RMW: no gpu-scope fence -> no CCTL.IVALL L1 flush (R3 lesson).
__device__ __forceinline__ int atomicAddAcqRelGpu(int* p, int v) {
    int old;
    asm volatile("atom.acq_rel.gpu.add.s32 %0, [%1], %2;"
                 : "=r"(old) : "l"(p), "r"(v) : "memory");
    return old;
}

// ---------------- kernel 1: fused prep (CTAs 0-3) + sort (CTA 4) ----------------
__global__ void __launch_bounds__(1024) prepsort_kernel(
                            const float* __restrict__ Ks,
                            const float* __restrict__ vm,
                            const float* __restrict__ means,
                            const float* __restrict__ quats,
                            const float* __restrict__ scales,
                            const float* __restrict__ ops,
                            const float* __restrict__ rgb)
{
    if (blockIdx.x < 4) {
        // ================= prep: one gaussian per thread =================
        int i = blockIdx.x * 1024 + threadIdx.x;
        if (blockIdx.x == 0 && threadIdx.x < N_TILES) g_cnt[threadIdx.x] = 0;

        float mx0 = means[i*3+0], my0 = means[i*3+1], mz0 = means[i*3+2];
        float qw = quats[i*4+0], qx = quats[i*4+1], qy = quats[i*4+2], qz = quats[i*4+3];
        float s0 = scales[i*3+0], s1 = scales[i*3+1], s2 = scales[i*3+2];
        float op = ops[i];
        float cr = rgb[i*3+0], cg = rgb[i*3+1], cb2 = rgb[i*3+2];

        float R00 = vm[0],  R01 = vm[1],  R02 = vm[2],  T0 = vm[3];
        float R10 = vm[4],  R11 = vm[5],  R12 = vm[6],  T1 = vm[7];
        float R20 = vm[8],  R21 = vm[9],  R22 = vm[10], T2 = vm[11];

        float x = R00*mx0 + R01*my0 + R02*mz0 + T0;
        float y = R10*mx0 + R11*my0 + R12*mz0 + T1;
        float z = R20*mx0 + R21*my0 + R22*mz0 + T2;

        float zs = (fabsf(z) < 1e-6f) ? 1e-6f : z;
        float rz = __fdividef(1.0f, zs);

        float qn = rsqrtf(qw*qw + qx*qx + qy*qy + qz*qz);
        qw *= qn; qx *= qn; qy *= qn; qz *= qn;
        float r00 = 1.f - 2.f*(qy*qy + qz*qz), r01 = 2.f*(qx*qy - qw*qz), r02 = 2.f*(qx*qz + qw*qy);
        float r10 = 2.f*(qx*qy + qw*qz), r11 = 1.f - 2.f*(qx*qx + qz*qz), r12 = 2.f*(qy*qz - qw*qx);
        float r20 = 2.f*(qx*qz - qw*qy), r21 = 2.f*(qy*qz + qw*qx), r22 = 1.f - 2.f*(qx*qx + qy*qy);

        float m00 = r00*s0, m01 = r01*s1, m02 = r02*s2;
        float m10 = r10*s0, m11 = r11*s1, m12 = r12*s2;
        float m20 = r20*s0, m21 = r21*s1, m22 = r22*s2;

        float c00 = m00*m00 + m01*m01 + m02*m02;
        float c01 = m00*m10 + m01*m11 + m02*m12;
        float c02 = m00*m20 + m01*m21 + m02*m22;
        float c11 = m10*m10 + m11*m11 + m12*m12;
        float c12 = m10*m20 + m11*m21 + m12*m22;
        float c22 = m20*m20 + m21*m21 + m22*m22;

        float t00 = R00*c00 + R01*c01 + R02*c02;
        float t01 = R00*c01 + R01*c11 + R02*c12;
        float t02 = R00*c02 + R01*c12 + R02*c22;
        float t10 = R10*c00 + R11*c01 + R12*c02;
        float t11 = R10*c01 + R11*c11 + R12*c12;
        float t12 = R10*c02 + R11*c12 + R12*c22;
        float t20 = R20*c00 + R21*c01 + R22*c02;
        float t21 = R20*c01 + R21*c11 + R22*c12;
        float t22 = R20*c02 + R21*c12 + R22*c22;
        float cc00 = t00*R00 + t01*R01 + t02*R02;
        float cc01 = t00*R10 + t01*R11 + t02*R12;
        float cc02 = t00*R20 + t01*R21 + t02*R22;
        float cc11 = t10*R10 + t11*R11 + t12*R12;
        float cc12 = t10*R20 + t11*R21 + t12*R22;
        float cc22 = t20*R20 + t21*R21 + t22*R22;

        float fx = Ks[0], fy = Ks[4], cxK = Ks[2], cyK = Ks[5];
        float j00 = fx*rz, j02 = -fx*x*rz*rz;
        float j11 = fy*rz, j12 = -fy*y*rz*rz;

        float a2 = j00*j00*cc00 + 2.f*j00*j02*cc02 + j02*j02*cc22;
        float b2 = j00*(cc01*j11 + cc02*j12) + j02*(cc12*j11 + cc22*j12);
        float c2 = j11*j11*cc11 + 2.f*j11*j12*cc12 + j12*j12*cc22;

        float a = a2 + EPS2D;
        float c = c2 + EPS2D;
        float b = b2;
        float det = a*c - b*b;
        bool valid = (z > 0.01f) && (z < 100.0f) && (det > 0.0f);
        float dets = (det > 0.0f) ? det : 1.0f;
        float rdet = __fdividef(1.0f, dets);
        float ica =  c * rdet;
        float icb = -b * rdet;
        float icc =  a * rdet;

        float mpx = fx*x*rz + cxK;
        float mpy = fy*y*rz + cyK;
        float smax = __logf(255.0f * op);

        float rx = -1.0f, ry = -1.0f;
        if (valid && smax > 0.0f) {
            float inv = 2.0f * smax * dets;
            rx = sqrtf(inv * icc) * 1.0001f + 0.01f;
            ry = sqrtf(inv * ica) * 1.0001f + 0.01f;
        }

        d_geo[i] = make_float4(mpx, mpy, rx, ry);
        d_con[i] = make_float4(0.5f*ica, icb, 0.5f*icc, op);
        d_col[i] = make_float4(cr, cg, cb2, smax + 0.02f);
        return;
    }

    // ================= sort: single CTA, all in shared =================
    __shared__ int            hist[NBUCKET];       // counts -> start -> cursor -> end
    __shared__ unsigned int   sk[N_GAUSS];
    __shared__ unsigned short si[N_GAUSS];
    __shared__ int            warpsums[32];

    const int t = threadIdx.x;           // 1024 threads
    const int lane = t & 31, wid = t >> 5;

    float R20 = vm[8], R21 = vm[9], R22 = vm[10], T2 = vm[11];

    for (int i = t; i < NBUCKET; i += 1024) hist[i] = 0;
    __syncthreads();

    unsigned int keys[4];
    int buck[4];
    #pragma unroll
    for (int c = 0; c < 4; c++) {
        int i = c * 1024 + t;
        float z = R20*means[i*3+0] + R21*means[i*3+1] + R22*means[i*3+2] + T2;
        keys[c] = __float_as_uint(z);
        int b = z_bucket(z);
        buck[c] = b;
        atomicAdd(&hist[b], 1);
    }
    __syncthreads();

    int h0 = hist[t*4+0], h1 = hist[t*4+1], h2 = hist[t*4+2], h3 = hist[t*4+3];
    int s = h0 + h1 + h2 + h3;
    int sc = s;
    #pragma unroll
    for (int o = 1; o < 32; o <<= 1) {
        int v = __shfl_up_sync(0xffffffffu, sc, o);
        if (lane >= o) sc += v;
    }
    if (lane == 31) warpsums[wid] = sc;
    __syncthreads();
    if (wid == 0) {
        int v = warpsums[lane];
        int vs = v;
        #pragma unroll
        for (int o = 1; o < 32; o <<= 1) {
            int u = __shfl_up_sync(0xffffffffu, vs, o);
            if (lane >= o) vs += u;
        }
        warpsums[lane] = vs - v;
    }
    __syncthreads();
    int excl = (sc - s) + warpsums[wid];
    hist[t*4+0] = excl;
    hist[t*4+1] = excl + h0;
    hist[t*4+2] = excl + h0 + h1;
    hist[t*4+3] = excl + h0 + h1 + h2;
    __syncthreads();

    #pragma unroll
    for (int c = 0; c < 4; c++) {
        int i = c * 1024 + t;
        int pos = atomicAdd(&hist[buck[c]], 1);
        sk[pos] = keys[c];
        si[pos] = (unsigned short)i;
    }
    __syncthreads();

    #pragma unroll
    for (int c = 0; c < 4; c++) {
        int slot = c * 1024 + t;
        unsigned int k = sk[slot];
        int id = si[slot];
        int b = z_bucket(__uint_as_float(k));
        int lo = (b > 0) ? hist[b-1] : 0;    // end[b-1] == start[b]
        int hi = hist[b];                     // end[b]
        int rank = 0;
        for (int j = lo; j < hi; j++) {
            unsigned int kj = sk[j];
            int ij = si[j];
            rank += (kj < k) || (kj == k && ij < id);
        }
        d_order[lo + rank] = id;
    }
}

// ---------------- kernel 2: render + fused last-CTA combine ----------------
__global__ void __launch_bounds__(256) render_kernel(float* __restrict__ out)
{
    const int tile = blockIdx.x;      // 0..63
    const int seg  = blockIdx.y;      // 0..15
    const int tx = tile & 7, ty = tile >> 3;
    const int lx = threadIdx.x & 15, ly = threadIdx.x >> 4;
    const float px = tx*16 + lx + 0.5f;
    const float py = ty*16 + ly + 0.5f;
    const float tileX0 = tx*16 + 0.5f, tileX1 = tileX0 + 15.0f;
    const float tileY0 = ty*16 + 0.5f, tileY1 = tileY0 + 15.0f;

    __shared__ float2 smxy[SEG_LEN];
    __shared__ float4 scon[SEG_LEN];
    __shared__ float4 scol[SEG_LEN];
    __shared__ int swcnt[8];
    __shared__ int sIsLast;

    const int lane = threadIdx.x & 31;
    const int wid  = threadIdx.x >> 5;

    // cull + compact this segment's 256 gaussians into shared (via d_order)
    int ord = d_order[seg * SEG_LEN + threadIdx.x];
    float4 geo = d_geo[ord];
    bool flag = (geo.z > 0.0f)
             && (geo.x + geo.z >= tileX0) && (geo.x - geo.z <= tileX1)
             && (geo.y + geo.w >= tileY0) && (geo.y - geo.w <= tileY1);
    unsigned m = __ballot_sync(0xffffffffu, flag);
    if (lane == 0) swcnt[wid] = __popc(m);
    __syncthreads();
    int base = 0, total = 0;
    #pragma unroll
    for (int w = 0; w < 8; w++) {
        int cw = swcnt[w];
        if (w < wid) base += cw;
        total += cw;
    }
    int pos = base + __popc(m & ((1u << lane) - 1u));
    if (flag) {
        smxy[pos] = make_float2(geo.x, geo.y);
        scon[pos] = d_con[ord];
        scol[pos] = d_col[ord];
    }
    __syncthreads();

    float T = 1.0f, Cr = 0.0f, Cg = 0.0f, Cb = 0.0f;

    for (int i = 0; i < total; i++) {
        if ((i & 31) == 0 && __all_sync(0xffffffffu, T < 1e-6f)) break;
        float2 mu = smxy[i];
        float4 co = scon[i];           // (0.5a, b, 0.5c, op)
        float dx = px - mu.x;
        float dy = py - mu.y;
        float sig = fmaf(co.x, dx*dx, fmaf(co.z, dy*dy, co.y*(dx*dy)));
        float4 col = scol[i];          // (r, g, b, cutoff)
        bool pre = (sig >= 0.0f) && (sig <= col.w);
        if (__any_sync(0xffffffffu, pre)) {
            float al = fminf(co.w * __expf(-sig), ALPHA_MAX);
            bool keep = (sig >= 0.0f) && (al >= ALPHA_MIN);
            float w = keep ? al * T : 0.0f;
            Cr = fmaf(w, col.x, Cr);
            Cg = fmaf(w, col.y, Cg);
            Cb = fmaf(w, col.z, Cb);
            T -= w;
        }
    }

    g_seg[(tile * N_SEG + seg) * TILE_PX + threadIdx.x] = make_float4(Cr, Cg, Cb, T);

    // last CTA of this tile combines the 16 segment partials.
    __syncthreads();   // all partial stores issued before the release-RMW
    if (threadIdx.x == 0)
        sIsLast = (atomicAddAcqRelGpu(&g_cnt[tile], 1) == N_SEG - 1) ? 1 : 0;
    __syncthreads();   // broadcast + ordering after t0's acquire

    if (sIsLast) {
        const float4* basep = &g_seg[tile * N_SEG * TILE_PX + threadIdx.x];
        float aCr = 0.0f, aCg = 0.0f, aCb = 0.0f, aT = 1.0f;
        #pragma unroll
        for (int s = 0; s < N_SEG; s++) {
            float4 p = __ldcg(basep + s * TILE_PX);   // L1-bypass: reads L2
            aCr = fmaf(aT, p.x, aCr);
            aCg = fmaf(aT, p.y, aCg);
            aCb = fmaf(aT, p.z, aCb);
            aT *= p.w;
        }
        int x = tx*16 + lx, y = ty*16 + ly;
        int p = y * IMG_W + x;
        out[p]                 = aCr;
        out[IMG_H*IMG_W + p]   = aCg;
        out[2*IMG_H*IMG_W + p] = aCb;
    }
}

// ---------------- launch ----------------
extern "C" void kernel_launch(void* const* d_in, const int* in_sizes, int n_in,
                              void* d_out, int out_size)
{
    const float* Ks     = (const float*)d_in[0];
    const float* vm     = (const float*)d_in[1];
    const float* means  = (const float*)d_in[2];
    const float* quats  = (const float*)d_in[3];
    const float* scales = (const float*)d_in[4];
    const float* ops    = (const float*)d_in[5];
    const float* rgb    = (const float*)d_in[6];
    float* out = (float*)d_out;

    prepsort_kernel<<<5, 1024>>>(Ks, vm, means, quats, scales, ops, rgb);
    render_kernel<<<dim3(N_TILES, N_SEG), 256>>>(out);
}